// round 2
// baseline (speedup 1.0000x reference)
#include <cuda_runtime.h>
#include <math.h>

#define NPT 8192
#define L2E 1.4426950408889634f
#define LN2 0.6931471805599453f
#define LOG_AB -9.010913347279288f   // log(1/8192)

#define TILE 1024
#define RPW 8
#define THREADS 128
#define ROWS_CTA 32                   // 4 warps * 8 rows
#define CTA_PER_PROB (NPT / ROWS_CTA) // 256

// Persistent scratch (no allocation allowed anywhere)
__device__ float4 d_ptsX[NPT], d_ptsY[NPT];   // (x,y,z, |p|^2/2)
__device__ float  d_du[2][4][NPT];            // [parity][f,g,pp,qq][i]

__global__ void init_kernel(const float* __restrict__ X, const float* __restrict__ Y) {
    int i = blockIdx.x * blockDim.x + threadIdx.x;
    if (i >= NPT) return;
    float x0 = X[3*i], x1 = X[3*i+1], x2 = X[3*i+2];
    d_ptsX[i] = make_float4(x0, x1, x2, 0.5f * (x0*x0 + x1*x1 + x2*x2));
    float y0 = Y[3*i], y1 = Y[3*i+1], y2 = Y[3*i+2];
    d_ptsY[i] = make_float4(y0, y1, y2, 0.5f * (y0*y0 + y1*y1 + y2*y2));
    d_du[0][0][i] = 0.f; d_du[0][1][i] = 0.f;
    d_du[0][2][i] = 0.f; d_du[0][3][i] = 0.f;
}

// One launch = one Sinkhorn phase: all 4 softmin problems, two-pass (max, sum-exp).
// prob 0: f  <- reduce over Y with dual g   (rows = X)
// prob 1: g  <- reduce over X with dual f   (rows = Y)
// prob 2: pp <- reduce over X with dual pp  (rows = X)
// prob 3: qq <- reduce over Y with dual qq  (rows = Y)
__global__ void __launch_bounds__(THREADS, 8)
phase_kernel(float eps, int avg, int par) {
    __shared__ float4 tile[TILE];

    int prob = blockIdx.x >> 8;            // / CTA_PER_PROB
    int rb   = blockIdx.x & (CTA_PER_PROB - 1);

    const float4* __restrict__ cpts = (prob == 1 || prob == 2) ? d_ptsX : d_ptsY;
    const float4* __restrict__ rpts = (prob == 0 || prob == 2) ? d_ptsX : d_ptsY;
    int didx = (prob == 0) ? 1 : (prob == 1) ? 0 : prob;
    const float* __restrict__ cdual  = d_du[par][didx];
    const float* __restrict__ oldpot = d_du[par][prob];
    float* __restrict__ outpot       = d_du[par ^ 1][prob];

    int warp = threadIdx.x >> 5;
    int lane = threadIdx.x & 31;
    int row0 = rb * ROWS_CTA + warp * RPW;

    float sc = L2E / eps;          // logits in log2 units
    float k0 = L2E * LOG_AB;

    float a0[RPW], a1[RPW], a2[RPW], m[RPW];
#pragma unroll
    for (int r = 0; r < RPW; r++) {
        float4 p = rpts[row0 + r];
        a0[r] = p.x * sc; a1[r] = p.y * sc; a2[r] = p.z * sc;
        m[r] = -3.0e38f;
    }

    // ---------- Pass 1: row maxima (no exp) ----------
    for (int tb = 0; tb < NPT; tb += TILE) {
        for (int j = threadIdx.x; j < TILE; j += THREADS) {
            float4 p = cpts[tb + j];
            p.w = fmaf(sc, cdual[tb + j] - p.w, k0);   // cb_j
            tile[j] = p;
        }
        __syncthreads();
#pragma unroll 4
        for (int k = 0; k < TILE / 32; k++) {
            float4 c = tile[k * 32 + lane];
#pragma unroll
            for (int r = 0; r < RPW; r++) {
                float t = fmaf(a0[r], c.x, fmaf(a1[r], c.y, fmaf(a2[r], c.z, c.w)));
                m[r] = fmaxf(m[r], t);
            }
        }
        __syncthreads();
    }
#pragma unroll
    for (int r = 0; r < RPW; r++)
#pragma unroll
        for (int o = 16; o; o >>= 1)
            m[r] = fmaxf(m[r], __shfl_xor_sync(0xffffffffu, m[r], o));

    // ---------- Pass 2: sum of exp2(t - M), guaranteed t - M <= 0 ----------
    float S[RPW];
#pragma unroll
    for (int r = 0; r < RPW; r++) S[r] = 0.f;

    for (int tb = 0; tb < NPT; tb += TILE) {
        for (int j = threadIdx.x; j < TILE; j += THREADS) {
            float4 p = cpts[tb + j];
            p.w = fmaf(sc, cdual[tb + j] - p.w, k0);
            tile[j] = p;
        }
        __syncthreads();
#pragma unroll 4
        for (int k = 0; k < TILE / 32; k++) {
            float4 c = tile[k * 32 + lane];
#pragma unroll
            for (int r = 0; r < RPW; r++) {
                float t = fmaf(a0[r], c.x, fmaf(a1[r], c.y, fmaf(a2[r], c.z, c.w)));
                S[r] += exp2f(t - m[r]);
            }
        }
        __syncthreads();
    }
#pragma unroll
    for (int r = 0; r < RPW; r++)
#pragma unroll
        for (int o = 16; o; o >>= 1)
            S[r] += __shfl_xor_sync(0xffffffffu, S[r], o);

    if (lane == 0) {
#pragma unroll
        for (int r = 0; r < RPW; r++) {
            int row = row0 + r;
            float res = rpts[row].w - eps * LN2 * (m[r] + log2f(S[r]));
            outpot[row] = avg ? 0.5f * (oldpot[row] + res) : res;
        }
    }
}

__global__ void reduce_kernel(float* out, int out_size) {
    __shared__ double sh[256];
    double s = 0.0;
    for (int i = threadIdx.x; i < NPT; i += 256)
        s += (double)(d_du[1][0][i] - d_du[1][2][i])
           + (double)(d_du[1][1][i] - d_du[1][3][i]);
    sh[threadIdx.x] = s;
    __syncthreads();
    for (int o = 128; o > 0; o >>= 1) {
        if (threadIdx.x < o) sh[threadIdx.x] += sh[threadIdx.x + o];
        __syncthreads();
    }
    if (threadIdx.x == 0) {
        float v = (float)(sh[0] / (double)NPT);
        for (int k = 0; k < out_size; k++) out[k] = v;
    }
}

extern "C" void kernel_launch(void* const* d_in, const int* in_sizes, int n_in,
                              void* d_out, int out_size) {
    const float* X = (const float*)d_in[0];   // source_points [8192,3]
    const float* Y = (const float*)d_in[1];   // target_points [8192,3]

    // geomloss eps schedule (double, matches reference)
    double sched[96];
    int ns = 0;
    double e      = pow(2.0, 2.0);
    double target = pow(0.01, 2.0);
    double ratio  = pow(0.9, 2.0);
    while (e > target) { sched[ns++] = e; e *= ratio; }

    init_kernel<<<NPT / 256, 256>>>(X, Y);

    // phase 0: init (zero duals, avg=0, eps=sched[0])
    // phases 1..ns: scan over full schedule (avg=1)
    // phase ns+1: final extrapolation at eps_final (avg=0)
    for (int p = 0; p <= ns + 1; p++) {
        float eps; int avg;
        if (p == 0)       { eps = (float)sched[0];     avg = 0; }
        else if (p <= ns) { eps = (float)sched[p - 1]; avg = 1; }
        else              { eps = (float)target;       avg = 0; }
        phase_kernel<<<4 * CTA_PER_PROB, THREADS>>>(eps, avg, p & 1);
    }
    // ns+2 = 53 phases total; last write parity = (52+1)&1 = 1
    reduce_kernel<<<1, 256>>>((float*)d_out, out_size);
}

// round 3
// speedup vs baseline: 2.1931x; 2.1931x over previous
#include <cuda_runtime.h>
#include <math.h>

#define NPT 8192
#define L2E 1.4426950408889634f
#define LN2 0.6931471805599453f
#define K0  (-13.0f)                 // log2(1/8192) = L2E * log(1/8192), exact

#define TILE 1024
#define RPW 8
#define THREADS 128
#define ROWS_CTA 32                   // 4 warps * 8 rows
#define CTA_PER_PROB (NPT / ROWS_CTA) // 256

// Persistent scratch (no allocation allowed anywhere)
__device__ float4 d_ptsX[NPT], d_ptsY[NPT];   // (x,y,z, |p|^2/2)
__device__ float  d_du[2][4][NPT];            // [parity][f,g,pp,qq][i]
__device__ float  d_mx[2][4][NPT];            // tracked row max (log2 units)

__device__ __forceinline__ float ex2(float x) {
    float y; asm("ex2.approx.f32 %0, %1;" : "=f"(y) : "f"(x)); return y;
}

__global__ void init_kernel(const float* __restrict__ X, const float* __restrict__ Y) {
    int i = blockIdx.x * blockDim.x + threadIdx.x;
    if (i >= NPT) return;
    float x0 = X[3*i], x1 = X[3*i+1], x2 = X[3*i+2];
    d_ptsX[i] = make_float4(x0, x1, x2, 0.5f * (x0*x0 + x1*x1 + x2*x2));
    float y0 = Y[3*i], y1 = Y[3*i+1], y2 = Y[3*i+2];
    d_ptsY[i] = make_float4(y0, y1, y2, 0.5f * (y0*y0 + y1*y1 + y2*y2));
#pragma unroll
    for (int p = 0; p < 4; p++) {
        d_du[0][p][i] = 0.f;
        // safe initial max estimate for eps0=4: t <= L2E*3/eps0 + K0
        d_mx[0][p][i] = K0 + 3.0f * L2E / 4.0f;
    }
}

// One launch = one Sinkhorn phase, one-pass softmin with predicted safe max.
// prob 0: f  <- reduce over Y with dual g   (rows = X)
// prob 1: g  <- reduce over X with dual f   (rows = Y)
// prob 2: pp <- reduce over X with dual pp  (rows = X)
// prob 3: qq <- reduce over Y with dual qq  (rows = Y)
__global__ void __launch_bounds__(THREADS)
phase_kernel(float eps, float ratio_inv, int avg, int par) {
    __shared__ float4 tile[TILE];
    __shared__ int redo_flag;

    int prob = blockIdx.x >> 8;            // / CTA_PER_PROB
    int rb   = blockIdx.x & (CTA_PER_PROB - 1);

    const float4* __restrict__ cpts = (prob == 1 || prob == 2) ? d_ptsX : d_ptsY;
    const float4* __restrict__ rpts = (prob == 0 || prob == 2) ? d_ptsX : d_ptsY;
    int didx = (prob == 0) ? 1 : (prob == 1) ? 0 : prob;
    const float* __restrict__ cdual  = d_du[par][didx];
    const float* __restrict__ oldpot = d_du[par][prob];
    const float* __restrict__ oldmax = d_mx[par][prob];
    float* __restrict__ outpot       = d_du[par ^ 1][prob];
    float* __restrict__ outmax       = d_mx[par ^ 1][prob];

    int warp = threadIdx.x >> 5;
    int lane = threadIdx.x & 31;
    int row0 = rb * ROWS_CTA + warp * RPW;

    float sc = L2E / eps;                  // logits in log2 units

    float a0[RPW], a1[RPW], a2[RPW], M[RPW], m[RPW], S[RPW];
#pragma unroll
    for (int r = 0; r < RPW; r++) {
        float4 p = rpts[row0 + r];
        a0[r] = p.x * sc; a1[r] = p.y * sc; a2[r] = p.z * sc;
        // predicted safe max: (m_prev - K0) scales by eps_prev/eps; +4 slack
        M[r] = fmaf(oldmax[row0 + r] - K0, ratio_inv, K0 + 4.0f);
    }

    int pass = 0;
    while (true) {
#pragma unroll
        for (int r = 0; r < RPW; r++) { m[r] = -3.0e38f; S[r] = 0.f; }

        for (int tb = 0; tb < NPT; tb += TILE) {
            __syncthreads();
            for (int j = threadIdx.x; j < TILE; j += THREADS) {
                float4 p = cpts[tb + j];
                p.w = fmaf(sc, cdual[tb + j] - p.w, K0);   // column bias cb_j
                tile[j] = p;
            }
            __syncthreads();
#pragma unroll 4
            for (int k = 0; k < TILE / 32; k++) {
                float4 c = tile[k * 32 + lane];
#pragma unroll
                for (int r = 0; r < RPW; r++) {
                    float t = fmaf(a0[r], c.x, fmaf(a1[r], c.y, fmaf(a2[r], c.z, c.w)));
                    m[r] = fmaxf(m[r], t);
                    S[r] += ex2(t - M[r]);
                }
            }
        }

        // warp reduce: true max and sum (M uniform per row, so S adds directly)
#pragma unroll
        for (int r = 0; r < RPW; r++) {
#pragma unroll
            for (int o = 16; o; o >>= 1) {
                m[r] = fmaxf(m[r], __shfl_xor_sync(0xffffffffu, m[r], o));
                S[r] += __shfl_xor_sync(0xffffffffu, S[r], o);
            }
        }

        // safety check: need  -80 < m - M < 100  for S to be fp32-exact enough
        int ok = 1;
#pragma unroll
        for (int r = 0; r < RPW; r++) {
            float d = m[r] - M[r];
            if (!(d > -80.f && d < 100.f)) ok = 0;
        }
        __syncthreads();
        if (threadIdx.x == 0) redo_flag = 0;
        __syncthreads();
        if (!ok && lane == 0) redo_flag = 1;   // benign multi-writer, same value
        __syncthreads();
        if (redo_flag == 0 || pass == 1) break;
#pragma unroll
        for (int r = 0; r < RPW; r++) M[r] = m[r];  // exact max, retry once
        pass++;
    }

    if (lane == 0) {
#pragma unroll
        for (int r = 0; r < RPW; r++) {
            int row = row0 + r;
            float res = rpts[row].w - eps * LN2 * (M[r] + log2f(S[r]));
            outpot[row] = avg ? 0.5f * (oldpot[row] + res) : res;
            outmax[row] = m[r];
        }
    }
}

__global__ void reduce_kernel(float* out, int out_size) {
    __shared__ double sh[256];
    double s = 0.0;
    for (int i = threadIdx.x; i < NPT; i += 256)
        s += (double)(d_du[1][0][i] - d_du[1][2][i])
           + (double)(d_du[1][1][i] - d_du[1][3][i]);
    sh[threadIdx.x] = s;
    __syncthreads();
    for (int o = 128; o > 0; o >>= 1) {
        if (threadIdx.x < o) sh[threadIdx.x] += sh[threadIdx.x + o];
        __syncthreads();
    }
    if (threadIdx.x == 0) {
        float v = (float)(sh[0] / (double)NPT);
        for (int k = 0; k < out_size; k++) out[k] = v;
    }
}

extern "C" void kernel_launch(void* const* d_in, const int* in_sizes, int n_in,
                              void* d_out, int out_size) {
    const float* X = (const float*)d_in[0];   // source_points [8192,3]
    const float* Y = (const float*)d_in[1];   // target_points [8192,3]

    // geomloss eps schedule (double, matches reference)
    double sched[96];
    int ns = 0;
    double e      = pow(2.0, 2.0);
    double target = pow(0.01, 2.0);
    double ratio  = pow(0.9, 2.0);
    while (e > target) { sched[ns++] = e; e *= ratio; }

    init_kernel<<<NPT / 256, 256>>>(X, Y);

    // phase 0: init (zero duals, avg=0, eps=sched[0])
    // phases 1..ns: scan over full schedule (avg=1)
    // phase ns+1: final extrapolation at eps_final (avg=0)
    double eps_prev = sched[0];
    for (int p = 0; p <= ns + 1; p++) {
        double eps; int avg;
        if (p == 0)       { eps = sched[0];     avg = 0; }
        else if (p <= ns) { eps = sched[p - 1]; avg = 1; }
        else              { eps = target;       avg = 0; }
        float ratio_inv = (float)(eps_prev / eps);
        phase_kernel<<<4 * CTA_PER_PROB, THREADS>>>((float)eps, ratio_inv, avg, p & 1);
        eps_prev = eps;
    }
    // 53 phases total; last write parity = 1
    reduce_kernel<<<1, 256>>>((float*)d_out, out_size);
}